// round 16
// baseline (speedup 1.0000x reference)
#include <cuda_runtime.h>
#include <cuda_bf16.h>
#include <cstdint>

// Problem constants
#define N_TOT   32768
#define D_DIM   256
#define K_CODES 1024
#define Q_ELEMS 8388608
#define TAU     6e-4f

// Hybrid split: tensor codes 0..767 (16 chunks x 48), scalar codes 768..1023 (16/iter)
#define TCH     48

// smem geometry (bytes)
#define XP      136                  // xs pitch in b16
#define EP      264                  // es pitch in b16 (528B rows)
#define SO_XS   0                    // 256*136*2 = 69632
#define SO_ES   69632                // 48*528    = 25344 (also norm scratch / cand alias)
#define SO_SE   94976                // scalar e fp32 [256 d][16 codes] = 16384
#define SO_NORM 111360               // 128 floats
#define SO_FLAG 111872               // cnt + 128 ints (520)
#define SO_IDX  112392               // 128 ints
#define SO_RED  112904               // 8 floats
#define SMEM_TOTAL 112960

// Device scratch
__device__ float          g_enorm[K_CODES];
__device__ __nv_bfloat16  g_eb16[K_CODES * D_DIM];
__device__ float          g_partials[256];
__device__ int            g_hist[K_CODES];

__device__ __forceinline__ float warpReduceSum(float v) {
    #pragma unroll
    for (int o = 16; o > 0; o >>= 1) v += __shfl_down_sync(0xffffffffu, v, o);
    return v;
}
__device__ __forceinline__ uint32_t smem_u32(const void* p) {
    uint32_t a;
    asm("{ .reg .u64 t; cvta.to.shared.u64 t, %1; cvt.u32.u64 %0, t; }" : "=r"(a) : "l"(p));
    return a;
}
__device__ __forceinline__ uint32_t packbf(float lo, float hi) {
    return ((uint32_t)__bfloat16_as_ushort(__float2bfloat16(hi)) << 16)
         |  (uint32_t)__bfloat16_as_ushort(__float2bfloat16(lo));
}

#define LDM_X4_T(r0,r1,r2,r3, a)                                               \
    asm volatile("ldmatrix.sync.aligned.m8n8.x4.trans.shared.b16 {%0,%1,%2,%3}, [%4];" \
                 : "=r"(r0), "=r"(r1), "=r"(r2), "=r"(r3) : "r"(a))
#define LDM_X4(r0,r1,r2,r3, a)                                                 \
    asm volatile("ldmatrix.sync.aligned.m8n8.x4.shared.b16 {%0,%1,%2,%3}, [%4];" \
                 : "=r"(r0), "=r"(r1), "=r"(r2), "=r"(r3) : "r"(a))
#define MMA_BF16(c0,c1,c2,c3, a0,a1,a2,a3, b0,b1)                              \
    asm volatile("mma.sync.aligned.m16n8k16.row.col.f32.bf16.bf16.f32 "        \
                 "{%0,%1,%2,%3},{%4,%5,%6,%7},{%8,%9},{%0,%1,%2,%3};"          \
                 : "+f"(c0), "+f"(c1), "+f"(c2), "+f"(c3)                      \
                 : "r"(a0), "r"(a1), "r"(a2), "r"(a3), "r"(b0), "r"(b1))
#define CP_ASYNC16(dst, src)                                                   \
    asm volatile("cp.async.cg.shared.global [%0], [%1], 16;" :: "r"(dst), "l"(src))
#define CP_COMMIT() asm volatile("cp.async.commit_group;" ::: "memory")
#define CP_WAIT(n)  asm volatile("cp.async.wait_group %0;" :: "n"(n) : "memory")

__device__ __forceinline__ void ins4(float v, int k, float bv[4], int bi[4]) {
    if (v < bv[3] || (v == bv[3] && k < bi[3])) {
        bv[3] = v; bi[3] = k;
        #pragma unroll
        for (int t = 3; t > 0; t--) {
            if (bv[t] < bv[t-1] || (bv[t] == bv[t-1] && bi[t] < bi[t-1])) {
                float tv = bv[t]; bv[t] = bv[t-1]; bv[t-1] = tv;
                int   ti = bi[t]; bi[t] = bi[t-1]; bi[t-1] = ti;
            }
        }
    }
}
__device__ __forceinline__ void ins2(float v, int k, float bv[2], int bi[2]) {
    if (v < bv[1] || (v == bv[1] && k < bi[1])) {
        bv[1] = v; bi[1] = k;
        if (bv[1] < bv[0] || (bv[1] == bv[0] && bi[1] < bi[0])) {
            float tv = bv[0]; bv[0] = bv[1]; bv[1] = tv;
            int   ti = bi[0]; bi[0] = bi[1]; bi[1] = ti;
        }
    }
}

// ---------------------------------------------------------------------------
// 1) prep: ||e_k||^2 + e->bf16 + zero hist. grid=128, block=256 (1 warp/code)
// ---------------------------------------------------------------------------
__global__ void prep_kernel(const float* __restrict__ emb) {
    int t = threadIdx.x;
    int lane = t & 31;
    int k = blockIdx.x * 8 + (t >> 5);
    const float4* src = (const float4*)(emb + ((size_t)k << 8));
    float4 a = src[lane * 2];
    float4 c = src[lane * 2 + 1];
    uint4 u;
    u.x = packbf(a.x, a.y); u.y = packbf(a.z, a.w);
    u.z = packbf(c.x, c.y); u.w = packbf(c.z, c.w);
    *(uint4*)(g_eb16 + ((size_t)k << 8) + lane * 8) = u;
    float ss = 0.f;
    ss = fmaf(a.x, a.x, ss); ss = fmaf(a.y, a.y, ss);
    ss = fmaf(a.z, a.z, ss); ss = fmaf(a.w, a.w, ss);
    ss = fmaf(c.x, c.x, ss); ss = fmaf(c.y, c.y, ss);
    ss = fmaf(c.z, c.z, ss); ss = fmaf(c.w, c.w, ss);
    ss = warpReduceSum(ss);
    if (lane == 0) g_enorm[k] = ss;
    if (blockIdx.x == 0) {
        for (int i = t; i < K_CODES; i += 256) g_hist[i] = 0;
    }
}

// ---------------------------------------------------------------------------
// 2) hybrid tensor(768 codes) + scalar-FMA(256 codes) argmin, fused everything.
//    grid=256, block=256, 2 CTA/SM -> one wave.
// ---------------------------------------------------------------------------
__global__ void __launch_bounds__(256, 2)
argmin_hyb_kernel(const float* __restrict__ x, const float* __restrict__ embf,
                  float* __restrict__ out, int out_size) {
    extern __shared__ __align__(16) char smem[];
    __nv_bfloat16* xs = (__nv_bfloat16*)(smem + SO_XS);   // [256 d][XP]
    float* norms = (float*)(smem + SO_NORM);
    int*   flagc = (int*)(smem + SO_FLAG);
    int*   flagr = flagc + 1;
    int*   idx_s = (int*)(smem + SO_IDX);

    const int tid  = threadIdx.x;
    const int lane = tid & 31;
    const int w    = tid >> 5;           // 0..7 = tensor row group
    const int g4   = lane >> 2;
    const int tg   = lane & 3;
    const int R    = w << 4;
    const int n0   = blockIdx.x << 7;
    const int b    = n0 >> 10;
    const int hw0  = n0 & 1023;
    const float* xb = x + ((size_t)b << 18) + hw0;

    const uint32_t es_u = smem_u32(smem + SO_ES);
    const uint32_t se_u = smem_u32(smem + SO_SE);

    // scalar mapping: 2 rows x 4 codes per thread
    const int sr0 = (tid & 63) << 1;     // rows sr0, sr0+1
    const int cg  = tid >> 6;            // code group 0..3 (uniform per warp)

    if (tid == 0) *flagc = 0;

    // ---- fill xs (bf16) + fused fp32 norm partials (single x read) ----
    {
        const int r8f = (tid & 15) << 3;
        const int dco = tid >> 4;
        float na8[8];
        #pragma unroll
        for (int j = 0; j < 8; j++) na8[j] = 0.f;
        #pragma unroll
        for (int i = 0; i < 16; i++) {
            int d = (i << 4) + dco;
            float4 t0 = *(const float4*)(xb + ((size_t)d << 10) + r8f);
            float4 t1 = *(const float4*)(xb + ((size_t)d << 10) + r8f + 4);
            na8[0] = fmaf(t0.x, t0.x, na8[0]);
            na8[1] = fmaf(t0.y, t0.y, na8[1]);
            na8[2] = fmaf(t0.z, t0.z, na8[2]);
            na8[3] = fmaf(t0.w, t0.w, na8[3]);
            na8[4] = fmaf(t1.x, t1.x, na8[4]);
            na8[5] = fmaf(t1.y, t1.y, na8[5]);
            na8[6] = fmaf(t1.z, t1.z, na8[6]);
            na8[7] = fmaf(t1.w, t1.w, na8[7]);
            uint4 u;
            u.x = packbf(t0.x, t0.y); u.y = packbf(t0.z, t0.w);
            u.z = packbf(t1.x, t1.y); u.w = packbf(t1.z, t1.w);
            *(uint4*)&xs[d * XP + r8f] = u;
        }
        float* scr = (float*)(smem + SO_ES);   // [row][16] partials (pre-staging)
        #pragma unroll
        for (int j = 0; j < 8; j++) scr[(r8f + j) * 16 + dco] = na8[j];
    }
    __syncthreads();
    if (tid < 128) {
        const float* p = (const float*)(smem + SO_ES) + tid * 16;
        float s = 0.f;
        #pragma unroll
        for (int j = 0; j < 16; j++) s += p[j];
        norms[tid] = s;
    }
    __syncthreads();   // norms done; ES scratch dead -> stage

    // ---- stage tensor chunk 0 (48 codes) + scalar-e slab 0 (16 codes fp32) ----
    #pragma unroll
    for (int it = 0; it < 6; it++) {
        int lin = it * 256 + tid;        // 0..1535
        int c   = lin >> 5;              // 0..47
        int sg  = lin & 31;
        CP_ASYNC16(es_u + (uint32_t)(c * (EP * 2) + sg * 16),
                   (const void*)(g_eb16 + ((size_t)c << 8) + sg * 8));
    }
    CP_COMMIT();
    {
        int c  = tid & 15;
        int bq = tid >> 4;               // 0..15
        #pragma unroll
        for (int i = 0; i < 4; i++) {
            int blk = bq + (i << 4);     // 0..63 (4 d's each)
            float4 t = *(const float4*)(embf + ((size_t)(768 + c) << 8) + (blk << 2));
            int d = blk << 2;
            *(float*)(smem + SO_SE + (d + 0) * 64 + c * 4) = t.x;
            *(float*)(smem + SO_SE + (d + 1) * 64 + c * 4) = t.y;
            *(float*)(smem + SO_SE + (d + 2) * 64 + c * 4) = t.z;
            *(float*)(smem + SO_SE + (d + 3) * 64 + c * 4) = t.w;
        }
    }
    CP_WAIT(0);
    __syncthreads();

    const float na0 = norms[R + g4];
    const float na1 = norms[R + g4 + 8];
    const float nr0 = norms[sr0];
    const float nr1 = norms[sr0 + 1];

    // per-lane ldmatrix addressing
    const uint32_t xs_u = smem_u32(xs);
    const int i8  = lane & 7;
    const int sel = lane >> 3;
    const uint32_t a_base = xs_u
        + (uint32_t)(((i8 + ((sel & 2) ? 8 : 0)) * XP + R + ((sel & 1) ? 8 : 0)) * 2);
    uint32_t b_off[3];
    #pragma unroll
    for (int p = 0; p < 3; p++)
        b_off[p] = (uint32_t)(((p * 16 + i8 + ((sel & 2) ? 8 : 0)) * EP) * 2
                              + ((sel & 1) ? 16 : 0));
    // scalar x address (rows sr0, sr0+1 adjacent -> one 4B LDS)
    const uint32_t sx_base = xs_u + (uint32_t)(sr0 * 2);
    const uint32_t se_base = se_u + (uint32_t)(cg * 16);

    float bva[4], bvb[4]; int bia[4], bib[4];
    #pragma unroll
    for (int j = 0; j < 4; j++) {
        bva[j] = 3.4e38f; bvb[j] = 3.4e38f;
        bia[j] = 0x7fffffff; bib[j] = 0x7fffffff;
    }
    float sv0[2], sv1[2]; int si0[2], si1[2];
    #pragma unroll
    for (int j = 0; j < 2; j++) {
        sv0[j] = 3.4e38f; sv1[j] = 3.4e38f;
        si0[j] = 0x7fffffff; si1[j] = 0x7fffffff;
    }

    for (int chunk = 0; chunk < 16; chunk++) {
        float acc[6][4];
        #pragma unroll
        for (int j = 0; j < 6; j++)
            #pragma unroll
            for (int q = 0; q < 4; q++) acc[j][q] = 0.f;
        float sac[2][4];
        #pragma unroll
        for (int m = 0; m < 2; m++)
            #pragma unroll
            for (int q = 0; q < 4; q++) sac[m][q] = 0.f;

        // interleaved: per K-step issue MMA group then 16 d of scalar FFMA
        #pragma unroll
        for (int K = 0; K < 256; K += 16) {
            uint32_t a0, a1, a2, a3;
            LDM_X4_T(a0, a1, a2, a3, a_base + (uint32_t)(K * XP * 2));
            #pragma unroll
            for (int p = 0; p < 3; p++) {
                uint32_t r0, r1, r2, r3;
                LDM_X4(r0, r1, r2, r3, es_u + b_off[p] + (uint32_t)(K * 2));
                MMA_BF16(acc[2*p][0], acc[2*p][1], acc[2*p][2], acc[2*p][3],
                         a0, a1, a2, a3, r0, r1);
                MMA_BF16(acc[2*p+1][0], acc[2*p+1][1], acc[2*p+1][2], acc[2*p+1][3],
                         a0, a1, a2, a3, r2, r3);
            }
            // scalar slab: d = K..K+15
            #pragma unroll
            for (int dd = 0; dd < 16; dd++) {
                int d = K + dd;
                uint32_t xp_;
                asm volatile("ld.shared.b32 %0, [%1];" : "=r"(xp_)
                             : "r"(sx_base + (uint32_t)(d * (XP * 2))));
                float x0 = __uint_as_float(xp_ << 16);
                float x1 = __uint_as_float(xp_ & 0xffff0000u);
                float4 ev = *(const float4*)(smem + SO_SE + d * 64 + cg * 16);
                sac[0][0] = fmaf(x0, ev.x, sac[0][0]);
                sac[0][1] = fmaf(x0, ev.y, sac[0][1]);
                sac[0][2] = fmaf(x0, ev.z, sac[0][2]);
                sac[0][3] = fmaf(x0, ev.w, sac[0][3]);
                sac[1][0] = fmaf(x1, ev.x, sac[1][0]);
                sac[1][1] = fmaf(x1, ev.y, sac[1][1]);
                sac[1][2] = fmaf(x1, ev.z, sac[1][2]);
                sac[1][3] = fmaf(x1, ev.w, sac[1][3]);
            }
        }
        __syncthreads();   // es + se fully consumed -> restage
        if (chunk < 15) {
            #pragma unroll
            for (int it = 0; it < 6; it++) {
                int lin = it * 256 + tid;
                int c   = lin >> 5;
                int sg  = lin & 31;
                CP_ASYNC16(es_u + (uint32_t)(c * (EP * 2) + sg * 16),
                           (const void*)(g_eb16 + (((size_t)((chunk + 1) * TCH + c)) << 8) + sg * 8));
            }
            CP_COMMIT();
            {
                int c  = tid & 15;
                int bq = tid >> 4;
                #pragma unroll
                for (int i = 0; i < 4; i++) {
                    int blk = bq + (i << 4);
                    float4 t = *(const float4*)(embf
                        + ((size_t)(768 + (chunk + 1) * 16 + c) << 8) + (blk << 2));
                    int d = blk << 2;
                    *(float*)(smem + SO_SE + (d + 0) * 64 + c * 4) = t.x;
                    *(float*)(smem + SO_SE + (d + 1) * 64 + c * 4) = t.y;
                    *(float*)(smem + SO_SE + (d + 2) * 64 + c * 4) = t.z;
                    *(float*)(smem + SO_SE + (d + 3) * 64 + c * 4) = t.w;
                }
            }
        }
        // tensor epilogue
        const int kb = chunk * TCH;
        #pragma unroll
        for (int j = 0; j < 6; j++) {
            int k0 = kb + (j >> 1) * 16 + (j & 1) * 8 + 2 * tg;
            float e0 = __ldg(&g_enorm[k0]);
            float e1 = __ldg(&g_enorm[k0 + 1]);
            ins4(fmaf(-2.f, acc[j][0], na0 + e0), k0,     bva, bia);
            ins4(fmaf(-2.f, acc[j][1], na0 + e1), k0 + 1, bva, bia);
            ins4(fmaf(-2.f, acc[j][2], na1 + e0), k0,     bvb, bib);
            ins4(fmaf(-2.f, acc[j][3], na1 + e1), k0 + 1, bvb, bib);
        }
        // scalar epilogue
        {
            int kcc = 768 + chunk * 16 + cg * 4;
            #pragma unroll
            for (int j = 0; j < 4; j++) {
                int k = kcc + j;
                float en = __ldg(&g_enorm[k]);
                ins2(fmaf(-2.f, sac[0][j], nr0 + en), k, sv0, si0);
                ins2(fmaf(-2.f, sac[1][j], nr1 + en), k, sv1, si1);
            }
        }
        if (chunk < 15) CP_WAIT(0);
        __syncthreads();
    }

    // ---- candidate staging (alias ES; all reads done) ----
    float* cand_v = (float*)(smem + SO_ES);              // [128][24]
    int*   cand_i = (int*)(smem + SO_ES + 12288);
    {
        int ra = R + g4, rb = R + g4 + 8;
        int s0 = tg * 4;
        #pragma unroll
        for (int j = 0; j < 4; j++) {
            cand_v[ra * 24 + s0 + j] = bva[j];
            cand_i[ra * 24 + s0 + j] = bia[j];
            cand_v[rb * 24 + s0 + j] = bvb[j];
            cand_i[rb * 24 + s0 + j] = bib[j];
        }
    }
    __syncthreads();
    {
        int o0 = sr0 * 24 + 16 + cg * 2;
        int o1 = (sr0 + 1) * 24 + 16 + cg * 2;
        #pragma unroll
        for (int j = 0; j < 2; j++) {
            cand_v[o0 + j] = sv0[j];  cand_i[o0 + j] = si0[j];
            cand_v[o1 + j] = sv1[j];  cand_i[o1 + j] = si1[j];
        }
    }
    __syncthreads();

    // ---- decision per row ----
    if (tid < 128) {
        int r = tid;
        float vm = cand_v[r * 24]; int im = cand_i[r * 24];
        #pragma unroll
        for (int j = 1; j < 24; j++) {
            float v = cand_v[r * 24 + j]; int k = cand_i[r * 24 + j];
            if (v < vm || (v == vm && k < im)) { vm = v; im = k; }
        }
        int cnt = 0;
        #pragma unroll
        for (int j = 0; j < 24; j++) cnt += (cand_v[r * 24 + j] <= vm + TAU);
        if (cnt == 1) {
            idx_s[r] = im;
        } else {
            int slot = atomicAdd(flagc, 1);
            flagr[slot] = r;
        }
    }
    __syncthreads();

    // ---- fused exact rescue: warp per flagged row ----
    const int nflag = *flagc;
    for (int f = w; f < nflag; f += 8) {
        int r = flagr[f];
        const float* xr = xb + r;
        float xv[8];
        #pragma unroll
        for (int t = 0; t < 8; t++) xv[t] = xr[(size_t)(lane + (t << 5)) << 10];
        float a = norms[r];

        float vmin = cand_v[r * 24];
        #pragma unroll
        for (int j = 1; j < 24; j++) vmin = fminf(vmin, cand_v[r * 24 + j]);

        float bestv = 3.4e38f; int besti = 0x7fffffff;
        for (int j = 0; j < 24; j++) {
            float cv = cand_v[r * 24 + j];
            if (cv > vmin + TAU) continue;
            int k = cand_i[r * 24 + j];
            const float* er = embf + ((size_t)k << 8);
            float d = 0.f;
            #pragma unroll
            for (int t = 0; t < 8; t++) d = fmaf(xv[t], er[lane + (t << 5)], d);
            #pragma unroll
            for (int o = 16; o > 0; o >>= 1) d += __shfl_xor_sync(0xffffffffu, d, o);
            float vv = fmaf(-2.f, d, a + __ldg(&g_enorm[k]));   // fl(fl(a+b) - 2*dot)
            if (vv < bestv || (vv == bestv && k < besti)) { bestv = vv; besti = k; }
        }
        if (lane == 0) idx_s[r] = besti;
    }
    __syncthreads();

    // ---- fused hist + index writeout ----
    if (tid < 128) {
        int idx = idx_s[tid];
        atomicAdd(&g_hist[idx], 1);
        if (out_size >= Q_ELEMS + 2 + N_TOT)
            out[Q_ELEMS + 2 + n0 + tid] = (float)idx;
    }

    // ---- fused gather + SSE for this CTA's 128 rows ----
    float sse = 0.f;
    #pragma unroll
    for (int u = 0; u < 32; u++) {
        int lin = u * 256 + tid;
        int r   = lin & 127;
        int d4  = lin >> 7;
        int idx = idx_s[r];
        float4 q = *(const float4*)(embf + ((size_t)idx << 8) + (d4 << 2));
        const float* xp = xb + ((size_t)(d4 << 2) << 10) + r;
        float* op = out + ((size_t)b << 18) + ((size_t)(d4 << 2) << 10) + hw0 + r;
        float qv[4] = {q.x, q.y, q.z, q.w};
        #pragma unroll
        for (int j = 0; j < 4; j++) {
            float xvj = xp[(size_t)j << 10];
            op[(size_t)j << 10] = qv[j];
            float dd = qv[j] - xvj;
            sse = fmaf(dd, dd, sse);
        }
    }
    {
        float* red = (float*)(smem + SO_RED);
        sse = warpReduceSum(sse);
        if (lane == 0) red[w] = sse;
        __syncthreads();
        if (tid < 8) {
            float v = red[tid];
            #pragma unroll
            for (int o = 4; o > 0; o >>= 1) v += __shfl_down_sync(0xffu, v, o);
            if (tid == 0) g_partials[blockIdx.x] = v;
        }
    }
}

// ---------------------------------------------------------------------------
// 3) finalize: loss + perplexity. grid=1, block=1024
// ---------------------------------------------------------------------------
__global__ void finalize_kernel(float* __restrict__ out, int out_size) {
    __shared__ float red[32];
    int tid = threadIdx.x;
    float s = (tid < 256) ? g_partials[tid] : 0.f;
    s = warpReduceSum(s);
    if ((tid & 31) == 0) red[tid >> 5] = s;
    __syncthreads();
    if (tid < 32) {
        float v = red[tid];
        v = warpReduceSum(v);
        if (tid == 0 && out_size > Q_ELEMS)
            out[Q_ELEMS] = 1.25f * v / (float)Q_ELEMS;
    }
    __syncthreads();
    float p = (float)g_hist[tid] / (float)N_TOT;
    float t = -p * logf(p + 1e-10f);
    t = warpReduceSum(t);
    if ((tid & 31) == 0) red[tid >> 5] = t;
    __syncthreads();
    if (tid < 32) {
        float v = red[tid];
        v = warpReduceSum(v);
        if (tid == 0 && out_size > Q_ELEMS + 1)
            out[Q_ELEMS + 1] = expf(v);
    }
}

// ---------------------------------------------------------------------------
extern "C" void kernel_launch(void* const* d_in, const int* in_sizes, int n_in,
                              void* d_out, int out_size) {
    const float* inputs = (const float*)d_in[0];
    const float* emb    = (const float*)d_in[1];
    if (n_in >= 2 && in_sizes[0] == K_CODES * D_DIM && in_sizes[1] == Q_ELEMS) {
        const float* t = inputs; inputs = emb; emb = t;
    }
    float* out = (float*)d_out;

    cudaFuncSetAttribute(argmin_hyb_kernel,
                         cudaFuncAttributeMaxDynamicSharedMemorySize, SMEM_TOTAL);

    prep_kernel<<<K_CODES / 8, 256>>>(emb);
    argmin_hyb_kernel<<<N_TOT / 128, 256, SMEM_TOTAL>>>(inputs, emb, out, out_size);
    finalize_kernel<<<1, 1024>>>(out, out_size);
}

// round 17
// speedup vs baseline: 1.7520x; 1.7520x over previous
#include <cuda_runtime.h>
#include <cuda_bf16.h>
#include <cstdint>

// Problem constants
#define N_TOT   32768
#define D_DIM   256
#define K_CODES 1024
#define Q_ELEMS 8388608
#define TAU     6e-4f

// smem geometry (bytes), 128-row CTA, single-buffered 64-code es
#define XP      136                  // xs pitch in b16 (272B, 16B-aligned rows)
#define EP      264                  // es pitch in b16 (528B)
#define SO_XS   0                    // 256*136*2 = 69632
#define SO_ES   69632                // 64*528 = 33792; [0,25344)=codes0-47, [25600,33792)=norm scratch
#define SO_NSC  (SO_ES + 25600)      // 2048 floats norm partials (freed before codes 48-63 staged)
#define SO_EN   103424               // 1024 floats
#define SO_NORM 107520               // 128 floats
#define SO_FLAG 108032               // cnt + 128 ints
#define SO_IDX  108552               // 128 ints
#define SO_RED  109064               // 8 floats
#define SMEM_TOTAL 110144

// Device scratch
__device__ float          g_enorm[K_CODES];
__device__ __nv_bfloat16  g_eb16[K_CODES * D_DIM];
__device__ float          g_partials[256];
__device__ int            g_hist[K_CODES];

__device__ __forceinline__ float warpReduceSum(float v) {
    #pragma unroll
    for (int o = 16; o > 0; o >>= 1) v += __shfl_down_sync(0xffffffffu, v, o);
    return v;
}
__device__ __forceinline__ uint32_t smem_u32(const void* p) {
    uint32_t a;
    asm("{ .reg .u64 t; cvta.to.shared.u64 t, %1; cvt.u32.u64 %0, t; }" : "=r"(a) : "l"(p));
    return a;
}
__device__ __forceinline__ uint32_t packbf(float lo, float hi) {
    return ((uint32_t)__bfloat16_as_ushort(__float2bfloat16(hi)) << 16)
         |  (uint32_t)__bfloat16_as_ushort(__float2bfloat16(lo));
}

#define LDM_X4_T(r0,r1,r2,r3, a)                                               \
    asm volatile("ldmatrix.sync.aligned.m8n8.x4.trans.shared.b16 {%0,%1,%2,%3}, [%4];" \
                 : "=r"(r0), "=r"(r1), "=r"(r2), "=r"(r3) : "r"(a))
#define LDM_X4(r0,r1,r2,r3, a)                                                 \
    asm volatile("ldmatrix.sync.aligned.m8n8.x4.shared.b16 {%0,%1,%2,%3}, [%4];" \
                 : "=r"(r0), "=r"(r1), "=r"(r2), "=r"(r3) : "r"(a))
#define MMA_BF16(c0,c1,c2,c3, a0,a1,a2,a3, b0,b1)                              \
    asm volatile("mma.sync.aligned.m16n8k16.row.col.f32.bf16.bf16.f32 "        \
                 "{%0,%1,%2,%3},{%4,%5,%6,%7},{%8,%9},{%0,%1,%2,%3};"          \
                 : "+f"(c0), "+f"(c1), "+f"(c2), "+f"(c3)                      \
                 : "r"(a0), "r"(a1), "r"(a2), "r"(a3), "r"(b0), "r"(b1))
#define CP_ASYNC16(dst, src)                                                   \
    asm volatile("cp.async.cg.shared.global [%0], [%1], 16;" :: "r"(dst), "l"(src))
#define CP_COMMIT() asm volatile("cp.async.commit_group;" ::: "memory")
#define CP_WAIT(n)  asm volatile("cp.async.wait_group %0;" :: "n"(n) : "memory")

__device__ __forceinline__ void ins4(float v, int k, float bv[4], int bi[4]) {
    if (v < bv[3] || (v == bv[3] && k < bi[3])) {
        bv[3] = v; bi[3] = k;
        #pragma unroll
        for (int t = 3; t > 0; t--) {
            if (bv[t] < bv[t-1] || (bv[t] == bv[t-1] && bi[t] < bi[t-1])) {
                float tv = bv[t]; bv[t] = bv[t-1]; bv[t-1] = tv;
                int   ti = bi[t]; bi[t] = bi[t-1]; bi[t-1] = ti;
            }
        }
    }
}

// ---------------------------------------------------------------------------
// 1) prep: ||e_k||^2 + e->bf16 + zero hist. grid=128, block=256 (1 warp/code)
// ---------------------------------------------------------------------------
__global__ void prep_kernel(const float* __restrict__ emb) {
    int t = threadIdx.x;
    int lane = t & 31;
    int k = blockIdx.x * 8 + (t >> 5);
    const float4* src = (const float4*)(emb + ((size_t)k << 8));
    float4 a = src[lane * 2];
    float4 c = src[lane * 2 + 1];
    uint4 u;
    u.x = packbf(a.x, a.y); u.y = packbf(a.z, a.w);
    u.z = packbf(c.x, c.y); u.w = packbf(c.z, c.w);
    *(uint4*)(g_eb16 + ((size_t)k << 8) + lane * 8) = u;
    float ss = 0.f;
    ss = fmaf(a.x, a.x, ss); ss = fmaf(a.y, a.y, ss);
    ss = fmaf(a.z, a.z, ss); ss = fmaf(a.w, a.w, ss);
    ss = fmaf(c.x, c.x, ss); ss = fmaf(c.y, c.y, ss);
    ss = fmaf(c.z, c.z, ss); ss = fmaf(c.w, c.w, ss);
    ss = warpReduceSum(ss);
    if (lane == 0) g_enorm[k] = ss;
    if (blockIdx.x == 0) {
        for (int i = t; i < K_CODES; i += 256) g_hist[i] = 0;
    }
}

// ---------------------------------------------------------------------------
// 2) bf16 mma.sync GEMM + best-4/lane + fused exact rescue + gather/SSE/hist.
//    CTA: 128 rows x 1024 codes (16 chunks of 64, single-buffered es).
//    Norms fused into the fill pass; chunk-0 codes 0-47 prefetch at entry.
//    8 warps = 8 row-groups of 16. grid=256, block=256, 2 CTA/SM -> one wave.
// ---------------------------------------------------------------------------
__global__ void __launch_bounds__(256, 2)
argmin_bf16_kernel(const float* __restrict__ x, const float* __restrict__ embf,
                   float* __restrict__ out, int out_size) {
    extern __shared__ __align__(16) char smem[];
    __nv_bfloat16* xs = (__nv_bfloat16*)(smem + SO_XS);   // [256 d][XP]
    float* en_s  = (float*)(smem + SO_EN);
    float* norms = (float*)(smem + SO_NORM);
    int*   flagc = (int*)(smem + SO_FLAG);
    int*   flagr = flagc + 1;
    int*   idx_s = (int*)(smem + SO_IDX);

    const int tid  = threadIdx.x;
    const int lane = tid & 31;
    const int w    = tid >> 5;           // 0..7 = row group
    const int g4   = lane >> 2;
    const int tg   = lane & 3;
    const int R    = w << 4;
    const int n0   = blockIdx.x << 7;
    const int b    = n0 >> 10;
    const int hw0  = n0 & 1023;
    const float* xb = x + ((size_t)b << 18) + hw0;

    const uint32_t es_u = smem_u32(smem + SO_ES);

    // ---- entry prefetch: chunk-0 codes 0..47 (disjoint from norm scratch) ----
    #pragma unroll
    for (int it = 0; it < 6; it++) {
        int lin = it * 256 + tid;        // 0..1535
        int c   = lin >> 5;              // code 0..47
        int sg  = lin & 31;              // 16B segment
        CP_ASYNC16(es_u + (uint32_t)(c * (EP * 2) + sg * 16),
                   (const void*)(g_eb16 + ((size_t)c << 8) + sg * 8));
    }
    CP_COMMIT();
    if (tid == 0) *flagc = 0;

    // ---- fill xs (bf16) + fused fp32 norm partials (single x read) ----
    {
        const int r8f = (tid & 15) << 3;
        const int dco = tid >> 4;
        float na8[8];
        #pragma unroll
        for (int j = 0; j < 8; j++) na8[j] = 0.f;
        #pragma unroll
        for (int i = 0; i < 16; i++) {
            int d = (i << 4) + dco;
            float4 t0 = *(const float4*)(xb + ((size_t)d << 10) + r8f);
            float4 t1 = *(const float4*)(xb + ((size_t)d << 10) + r8f + 4);
            na8[0] = fmaf(t0.x, t0.x, na8[0]);
            na8[1] = fmaf(t0.y, t0.y, na8[1]);
            na8[2] = fmaf(t0.z, t0.z, na8[2]);
            na8[3] = fmaf(t0.w, t0.w, na8[3]);
            na8[4] = fmaf(t1.x, t1.x, na8[4]);
            na8[5] = fmaf(t1.y, t1.y, na8[5]);
            na8[6] = fmaf(t1.z, t1.z, na8[6]);
            na8[7] = fmaf(t1.w, t1.w, na8[7]);
            uint4 u;
            u.x = packbf(t0.x, t0.y); u.y = packbf(t0.z, t0.w);
            u.z = packbf(t1.x, t1.y); u.w = packbf(t1.z, t1.w);
            *(uint4*)&xs[d * XP + r8f] = u;
        }
        float* scr = (float*)(smem + SO_NSC);   // [row][16] partials
        #pragma unroll
        for (int j = 0; j < 8; j++) scr[(r8f + j) * 16 + dco] = na8[j];
    }
    for (int i = tid; i < K_CODES; i += 256) en_s[i] = g_enorm[i];
    __syncthreads();
    if (tid < 128) {
        const float* p = (const float*)(smem + SO_NSC) + tid * 16;
        float s = 0.f;
        #pragma unroll
        for (int j = 0; j < 16; j++) s += p[j];
        norms[tid] = s;
    }
    __syncthreads();   // norm scratch dead -> stage codes 48..63 over it

    #pragma unroll
    for (int it = 0; it < 2; it++) {
        int lin = it * 256 + tid;        // 0..511
        int c   = 48 + (lin >> 5);       // code 48..63
        int sg  = lin & 31;
        CP_ASYNC16(es_u + (uint32_t)(c * (EP * 2) + sg * 16),
                   (const void*)(g_eb16 + ((size_t)c << 8) + sg * 8));
    }
    CP_COMMIT();
    CP_WAIT(0);
    __syncthreads();

    const float na0 = norms[R + g4];
    const float na1 = norms[R + g4 + 8];

    // per-lane ldmatrix addressing
    const uint32_t xs_u = smem_u32(xs);
    const int i8  = lane & 7;
    const int sel = lane >> 3;
    const uint32_t a_base = xs_u
        + (uint32_t)(((i8 + ((sel & 2) ? 8 : 0)) * XP + R + ((sel & 1) ? 8 : 0)) * 2);
    uint32_t b_off[4];
    #pragma unroll
    for (int p = 0; p < 4; p++)
        b_off[p] = (uint32_t)(((p * 16 + i8 + ((sel & 2) ? 8 : 0)) * EP) * 2
                              + ((sel & 1) ? 16 : 0));

    float bva[4], bvb[4]; int bia[4], bib[4];
    #pragma unroll
    for (int j = 0; j < 4; j++) {
        bva[j] = 3.4e38f; bvb[j] = 3.4e38f;
        bia[j] = 0x7fffffff; bib[j] = 0x7fffffff;
    }

    for (int chunk = 0; chunk < 16; chunk++) {
        float acc[8][4];
        #pragma unroll
        for (int j = 0; j < 8; j++)
            #pragma unroll
            for (int q = 0; q < 4; q++) acc[j][q] = 0.f;

        #pragma unroll
        for (int K = 0; K < 256; K += 16) {
            uint32_t a0, a1, a2, a3;
            LDM_X4_T(a0, a1, a2, a3, a_base + (uint32_t)(K * XP * 2));
            #pragma unroll
            for (int p = 0; p < 4; p++) {
                uint32_t r0, r1, r2, r3;
                LDM_X4(r0, r1, r2, r3, es_u + b_off[p] + (uint32_t)(K * 2));
                MMA_BF16(acc[2*p][0], acc[2*p][1], acc[2*p][2], acc[2*p][3],
                         a0, a1, a2, a3, r0, r1);
                MMA_BF16(acc[2*p+1][0], acc[2*p+1][1], acc[2*p+1][2], acc[2*p+1][3],
                         a0, a1, a2, a3, r2, r3);
            }
        }
        __syncthreads();   // all warps done reading es before restage
        if (chunk < 15) {  // stage next chunk (single buffer)
            #pragma unroll
            for (int it = 0; it < 8; it++) {
                int lin = it * 256 + tid;
                int c   = lin >> 5;
                int sg  = lin & 31;
                CP_ASYNC16(es_u + (uint32_t)(c * (EP * 2) + sg * 16),
                           (const void*)(g_eb16 + (((size_t)((chunk + 1) * 64 + c)) << 8) + sg * 8));
            }
            CP_COMMIT();
        }
        // epilogue overlaps the cp.async in flight
        const int kb = chunk * 64;
        #pragma unroll
        for (int j = 0; j < 8; j++) {
            int k0 = kb + (j >> 1) * 16 + (j & 1) * 8 + 2 * tg;
            float e0 = en_s[k0], e1 = en_s[k0 + 1];
            ins4(fmaf(-2.f, acc[j][0], na0 + e0), k0,     bva, bia);
            ins4(fmaf(-2.f, acc[j][1], na0 + e1), k0 + 1, bva, bia);
            ins4(fmaf(-2.f, acc[j][2], na1 + e0), k0,     bvb, bib);
            ins4(fmaf(-2.f, acc[j][3], na1 + e1), k0 + 1, bvb, bib);
        }
        if (chunk < 15) CP_WAIT(0);
        __syncthreads();
    }

    // ---- candidate staging (alias es; all MMA reads done) ----
    float* cand_v = (float*)(smem + SO_ES);              // [128][16]
    int*   cand_i = (int*)(smem + SO_ES + 8192);
    {
        int ra = R + g4, rb = R + g4 + 8;
        int s0 = tg * 4;
        #pragma unroll
        for (int j = 0; j < 4; j++) {
            cand_v[ra * 16 + s0 + j] = bva[j];
            cand_i[ra * 16 + s0 + j] = bia[j];
            cand_v[rb * 16 + s0 + j] = bvb[j];
            cand_i[rb * 16 + s0 + j] = bib[j];
        }
    }
    __syncthreads();

    // ---- decision per row ----
    if (tid < 128) {
        int r = tid;
        float vm = cand_v[r * 16]; int im = cand_i[r * 16];
        #pragma unroll
        for (int j = 1; j < 16; j++) {
            float v = cand_v[r * 16 + j]; int k = cand_i[r * 16 + j];
            if (v < vm || (v == vm && k < im)) { vm = v; im = k; }
        }
        int cnt = 0;
        #pragma unroll
        for (int j = 0; j < 16; j++) cnt += (cand_v[r * 16 + j] <= vm + TAU);
        if (cnt == 1) {
            idx_s[r] = im;
        } else {
            int slot = atomicAdd(flagc, 1);
            flagr[slot] = r;
        }
    }
    __syncthreads();

    // ---- fused exact rescue: warp per flagged row ----
    const int nflag = *flagc;
    for (int f = w; f < nflag; f += 8) {
        int r = flagr[f];
        const float* xr = xb + r;
        float xv[8];
        #pragma unroll
        for (int t = 0; t < 8; t++) xv[t] = xr[(size_t)(lane + (t << 5)) << 10];
        float a = norms[r];   // exact fp32 (translation-invariant vs reference)

        float vmin = cand_v[r * 16];
        #pragma unroll
        for (int j = 1; j < 16; j++) vmin = fminf(vmin, cand_v[r * 16 + j]);

        float bestv = 3.4e38f; int besti = 0x7fffffff;
        for (int j = 0; j < 16; j++) {
            float cv = cand_v[r * 16 + j];
            if (cv > vmin + TAU) continue;
            int k = cand_i[r * 16 + j];
            const float* er = embf + ((size_t)k << 8);
            float d = 0.f;
            #pragma unroll
            for (int t = 0; t < 8; t++) d = fmaf(xv[t], er[lane + (t << 5)], d);
            #pragma unroll
            for (int o = 16; o > 0; o >>= 1) d += __shfl_xor_sync(0xffffffffu, d, o);
            float vv = fmaf(-2.f, d, a + en_s[k]);   // fl(fl(a+b) - 2*dot)
            if (vv < bestv || (vv == bestv && k < besti)) { bestv = vv; besti = k; }
        }
        if (lane == 0) idx_s[r] = besti;
    }
    __syncthreads();

    // ---- fused hist + index writeout ----
    if (tid < 128) {
        int idx = idx_s[tid];
        atomicAdd(&g_hist[idx], 1);
        if (out_size >= Q_ELEMS + 2 + N_TOT)
            out[Q_ELEMS + 2 + n0 + tid] = (float)idx;
    }

    // ---- fused gather + SSE for this CTA's 128 rows ----
    float sse = 0.f;
    #pragma unroll
    for (int u = 0; u < 32; u++) {
        int lin = u * 256 + tid;          // 0..8191
        int r   = lin & 127;
        int d4  = lin >> 7;               // 0..63
        int idx = idx_s[r];
        float4 q = *(const float4*)(embf + ((size_t)idx << 8) + (d4 << 2));
        const float* xp = xb + ((size_t)(d4 << 2) << 10) + r;
        float* op = out + ((size_t)b << 18) + ((size_t)(d4 << 2) << 10) + hw0 + r;
        float qv[4] = {q.x, q.y, q.z, q.w};
        #pragma unroll
        for (int j = 0; j < 4; j++) {
            float xvj = xp[(size_t)j << 10];
            op[(size_t)j << 10] = qv[j];
            float dd = qv[j] - xvj;
            sse = fmaf(dd, dd, sse);
        }
    }
    {
        float* red = (float*)(smem + SO_RED);
        sse = warpReduceSum(sse);
        if (lane == 0) red[w] = sse;
        __syncthreads();
        if (tid < 8) {
            float v = red[tid];
            #pragma unroll
            for (int o = 4; o > 0; o >>= 1) v += __shfl_down_sync(0xffu, v, o);
            if (tid == 0) g_partials[blockIdx.x] = v;
        }
    }
}

// ---------------------------------------------------------------------------
// 3) finalize: loss + perplexity. grid=1, block=1024
// ---------------------------------------------------------------------------
__global__ void finalize_kernel(float* __restrict__ out, int out_size) {
    __shared__ float red[32];
    int tid = threadIdx.x;
    float s = (tid < 256) ? g_partials[tid] : 0.f;
    s = warpReduceSum(s);
    if ((tid & 31) == 0) red[tid >> 5] = s;
    __syncthreads();
    if (tid < 32) {
        float v = red[tid];
        v = warpReduceSum(v);
        if (tid == 0 && out_size > Q_ELEMS)
            out[Q_ELEMS] = 1.25f * v / (float)Q_ELEMS;   // q_latent + 0.25*e_latent
    }
    __syncthreads();
    float p = (float)g_hist[tid] / (float)N_TOT;
    float t = -p * logf(p + 1e-10f);
    t = warpReduceSum(t);
    if ((tid & 31) == 0) red[tid >> 5] = t;
    __syncthreads();
    if (tid < 32) {
        float v = red[tid];
        v = warpReduceSum(v);
        if (tid == 0 && out_size > Q_ELEMS + 1)
            out[Q_ELEMS + 1] = expf(v);
    }
}

// ---------------------------------------------------------------------------
extern "C" void kernel_launch(void* const* d_in, const int* in_sizes, int n_in,
                              void* d_out, int out_size) {
    const float* inputs = (const float*)d_in[0];
    const float* emb    = (const float*)d_in[1];
    if (n_in >= 2 && in_sizes[0] == K_CODES * D_DIM && in_sizes[1] == Q_ELEMS) {
        const float* t = inputs; inputs = emb; emb = t;
    }
    float* out = (float*)d_out;

    cudaFuncSetAttribute(argmin_bf16_kernel,
                         cudaFuncAttributeMaxDynamicSharedMemorySize, SMEM_TOTAL);

    prep_kernel<<<K_CODES / 8, 256>>>(emb);
    argmin_bf16_kernel<<<N_TOT / 128, 256, SMEM_TOTAL>>>(inputs, emb, out, out_size);
    finalize_kernel<<<1, 1024>>>(out, out_size);
}